// round 10
// baseline (speedup 1.0000x reference)
#include <cuda_runtime.h>
#include <cuda_bf16.h>
#include <cstdint>
#include <cstddef>

#define DIMK     256
#define NBATCH   16
#define TILE_M   64
#define NTHREADS 256
#define NCHUNK   8

typedef unsigned long long u64;

// ---------------- device globals ----------------
__device__ float g_up[NBATCH * DIMK];                 // u@Wu + b1
__device__ __nv_bfloat16 g_Bhi[DIMK * DIMK];          // B[n][k] = Wi[k][n], hi
__device__ __nv_bfloat16 g_Blo[DIMK * DIMK];          // lo

// ---------------- smem layout (main): 97KB, 2 CTAs/SM ----------------
#define SM_B    0                    // 2 bufs x (16KB hi + 16KB lo) = 64KB
#define SM_PART 0                    // epilogue partials (16KB), reuses B
#define SM_A    (64 * 1024)          // 2 bufs x (4KB hi + 4KB lo) = 16KB
#define SM_UP   (80 * 1024)          // 16 x 256 fp32 = 16KB
#define SM_W2   (96 * 1024)          // 256 fp32 = 1KB
#define SMEM_TOTAL (97 * 1024)

// ---------------- helpers ----------------
__device__ __forceinline__ u64 pack2f(float lo, float hi) {
    u64 r; asm("mov.b64 %0, {%1, %2};" : "=l"(r) : "f"(lo), "f"(hi)); return r;
}
__device__ __forceinline__ void unpack2(u64 v, float& lo, float& hi) {
    asm("mov.b64 {%0, %1}, %2;" : "=f"(lo), "=f"(hi) : "l"(v));
}
__device__ __forceinline__ u64 add2(u64 a, u64 b) {
    u64 r; asm("add.rn.f32x2 %0, %1, %2;" : "=l"(r) : "l"(a), "l"(b)); return r;
}
__device__ __forceinline__ void ffma2(u64& d, u64 a, u64 b) {
    asm("fma.rn.f32x2 %0, %1, %2, %0;" : "+l"(d) : "l"(a), "l"(b));
}
__device__ __forceinline__ u64 relu2(u64 x) {
    u64 r;
    asm("{\n\t.reg .f32 lo, hi;\n\t"
        "mov.b64 {lo, hi}, %1;\n\t"
        "max.f32 lo, lo, 0f00000000;\n\t"
        "max.f32 hi, hi, 0f00000000;\n\t"
        "mov.b64 %0, {lo, hi};\n\t}" : "=l"(r) : "l"(x));
    return r;
}
__device__ __forceinline__ u64 lds_b64(uint32_t addr) {
    u64 r; asm volatile("ld.shared.b64 %0, [%1];" : "=l"(r) : "r"(addr)); return r;
}
__device__ __forceinline__ void cp_async16(uint32_t dst, const void* src) {
    asm volatile("cp.async.cg.shared.global [%0], [%1], 16;" :: "r"(dst), "l"(src));
}
__device__ __forceinline__ void ldsm4(uint32_t* r, uint32_t addr) {
    asm volatile("ldmatrix.sync.aligned.m8n8.x4.shared.b16 {%0,%1,%2,%3}, [%4];"
        : "=r"(r[0]), "=r"(r[1]), "=r"(r[2]), "=r"(r[3]) : "r"(addr));
}
__device__ __forceinline__ void mma16816(float* c, const uint32_t* a,
                                         uint32_t b0, uint32_t b1) {
    asm volatile("mma.sync.aligned.m16n8k16.row.col.f32.bf16.bf16.f32 "
        "{%0,%1,%2,%3}, {%4,%5,%6,%7}, {%8,%9}, {%0,%1,%2,%3};"
        : "+f"(c[0]), "+f"(c[1]), "+f"(c[2]), "+f"(c[3])
        : "r"(a[0]), "r"(a[1]), "r"(a[2]), "r"(a[3]), "r"(b0), "r"(b1));
}
__device__ __forceinline__ uint32_t split2h(float x, float y, uint32_t& lp) {
    __nv_bfloat16 h0 = __float2bfloat16(x);
    __nv_bfloat16 h1 = __float2bfloat16(y);
    __nv_bfloat16 l0 = __float2bfloat16(x - __bfloat162float(h0));
    __nv_bfloat16 l1 = __float2bfloat16(y - __bfloat162float(h1));
    __nv_bfloat162 hh; hh.x = h0; hh.y = h1;
    __nv_bfloat162 ll; ll.x = l0; ll.y = l1;
    lp = *reinterpret_cast<uint32_t*>(&ll);
    return *reinterpret_cast<uint32_t*>(&hh);
}
// row-pair layout: 64B logical rows packed into 128B smem rows, XOR-swizzled
__device__ __forceinline__ uint32_t swoff(int row, int kc) {
    uint32_t rp = (uint32_t)row >> 1;
    uint32_t c8 = (uint32_t)((row & 1) << 2) | (uint32_t)kc;
    return rp * 128u + ((c8 ^ (rp & 7u)) << 4);
}

// ---------------- fused pre: convB (blocks 0-7) + prep (blocks 8-23) ------
__global__ void pre_kernel(const int* __restrict__ inst,
                           const float* __restrict__ user_table,
                           const float* __restrict__ W1,
                           const float* __restrict__ b1) {
    __shared__ float sbuf[32 * 33];
    int tid = threadIdx.x;

    if (blockIdx.x < 8) {
        float (*tile)[33] = (float(*)[33])sbuf;
        const float* Wi = W1 + DIMK * DIMK;
        int n0 = blockIdx.x * 32;
        int tr = tid >> 5, tc = tid & 31;
        for (int kb = 0; kb < 8; kb++) {
#pragma unroll
            for (int p = 0; p < 4; p++) {
                int k = kb * 32 + p * 8 + tr;
                tile[p * 8 + tr][tc] = Wi[(size_t)k * DIMK + n0 + tc];
            }
            __syncthreads();
#pragma unroll
            for (int p = 0; p < 4; p++) {
                int nl = p * 8 + tr;
                float x = tile[tc][nl];
                __nv_bfloat16 h = __float2bfloat16(x);
                __nv_bfloat16 l = __float2bfloat16(x - __bfloat162float(h));
                size_t off = (size_t)(n0 + nl) * DIMK + kb * 32 + tc;
                g_Bhi[off] = h;
                g_Blo[off] = l;
            }
            __syncthreads();
        }
    } else {
        float* u = sbuf;
        int b = blockIdx.x - 8;
        bool w64 = true;
#pragma unroll
        for (int i = 1; i < 16; i += 2) w64 = w64 && (inst[i] == 0);
        int row = w64 ? inst[2 * b] : inst[b];
        if (tid < 64)
            ((float4*)u)[tid] = ((const float4*)(user_table + (size_t)row * DIMK))[tid];
        __syncthreads();
        int d = tid;
        float acc = 0.f;
#pragma unroll 8
        for (int k = 0; k < DIMK; k++)
            acc = fmaf(u[k], W1[(size_t)k * DIMK + d], acc);
        g_up[b * DIMK + d] = acc + b1[d];
    }
}

// ---------------- main: 2 CTA/SM, RAW-free 3-pass MMA schedule ------------
__global__ void __launch_bounds__(NTHREADS, 2)
main_kernel(const float* __restrict__ item,
            const float* __restrict__ W2v, const float* __restrict__ b2,
            float* __restrict__ out, int M) {
    extern __shared__ __align__(1024) char smem[];
    uint32_t sb = (uint32_t)__cvta_generic_to_shared(smem);
    int tid = threadIdx.x, wid = tid >> 5, lane = tid & 31;
    int mwarp = wid >> 2, nwarp = wid & 3;      // 2 x 4 warp grid
    int m0 = blockIdx.x * TILE_M;

    // stage up / w2
    for (int i = tid; i < NBATCH * DIMK; i += NTHREADS)
        ((float*)(smem + SM_UP))[i] = g_up[i];
    if (tid < 64)
        ((float4*)(smem + SM_W2))[tid] = ((const float4*)W2v)[tid];

    // B chunk c (32 k) -> buf: 16KB hi + 16KB lo
    auto loadB = [&](int c, int buf) {
        uint32_t base = sb + SM_B + (uint32_t)buf * 32768u;
#pragma unroll
        for (int i = 0; i < 4; i++) {
            int id = tid + i * NTHREADS;       // 0..1023
            int n = id >> 2, kc = id & 3;
            uint32_t d = base + swoff(n, kc);
            size_t g = (size_t)n * 512 + (size_t)c * 64 + (size_t)kc * 16;
            cp_async16(d,          (const char*)g_Bhi + g);
            cp_async16(d + 16384u, (const char*)g_Blo + g);
        }
        asm volatile("cp.async.commit_group;" ::: "memory");
    };

    // A: thread owns (row tid>>2, 8-k group kq=tid&3)
    float4 pre[2];
    auto loadA = [&](int c) {
        int r = tid >> 2, kq = tid & 3;
        int m = m0 + r;
        pre[0] = make_float4(0.f, 0.f, 0.f, 0.f);
        pre[1] = pre[0];
        if (m < M) {
            const float4* p = (const float4*)(item + (size_t)m * DIMK + c * 32 + kq * 8);
            pre[0] = p[0]; pre[1] = p[1];
        }
    };
    auto stsA = [&](int buf) {
        int r = tid >> 2, kq = tid & 3;
        uint32_t h[4], l[4];
        h[0] = split2h(pre[0].x, pre[0].y, l[0]);
        h[1] = split2h(pre[0].z, pre[0].w, l[1]);
        h[2] = split2h(pre[1].x, pre[1].y, l[2]);
        h[3] = split2h(pre[1].z, pre[1].w, l[3]);
        uint32_t off = SM_A + (uint32_t)buf * 8192u + swoff(r, kq);
        *(uint4*)(smem + off)        = make_uint4(h[0], h[1], h[2], h[3]);
        *(uint4*)(smem + off + 4096) = make_uint4(l[0], l[1], l[2], l[3]);
    };

    float acc0[8][4], acc1[8][4];
#pragma unroll
    for (int j = 0; j < 8; j++)
#pragma unroll
        for (int q = 0; q < 4; q++) { acc0[j][q] = 0.f; acc1[j][q] = 0.f; }

    loadB(0, 0);
    loadA(0);
    stsA(0);
    asm volatile("cp.async.wait_group 0;" ::: "memory");
    __syncthreads();

#pragma unroll 1
    for (int c = 0; c < NCHUNK; c++) {
        if (c < NCHUNK - 1) {
            loadB(c + 1, (c + 1) & 1);
            loadA(c + 1);
        }

        uint32_t ab = sb + SM_A + (uint32_t)(c & 1) * 8192u;
        uint32_t bb = sb + SM_B + (uint32_t)(c & 1) * 32768u;
#pragma unroll
        for (int ks = 0; ks < 2; ks++) {
            int akc = 2 * ks + (lane >> 4);
            uint32_t a0 = ab + swoff(mwarp * 32 + (lane & 15), akc);
            uint32_t a1 = ab + swoff(mwarp * 32 + 16 + (lane & 15), akc);
            uint32_t ah0[4], ah1[4], al0[4], al1[4];
            ldsm4(ah0, a0); ldsm4(ah1, a1);
            ldsm4(al0, a0 + 4096); ldsm4(al1, a1 + 4096);

            int brow7 = (lane & 7) + ((lane >> 4) & 1) * 8;
            int bkc = 2 * ks + ((lane >> 3) & 1);

            // load ALL B fragments for this ks (8 ldsm4, 32 regs)
            uint32_t bh[4][4], bl[4][4];
#pragma unroll
            for (int ng = 0; ng < 4; ng++) {
                uint32_t bo = bb + swoff(nwarp * 64 + ng * 16 + brow7, bkc);
                ldsm4(bh[ng], bo);
                ldsm4(bl[ng], bo + 16384);
            }
            // pass 1: hi*hi — 16 independent MMAs
#pragma unroll
            for (int ng = 0; ng < 4; ng++) {
                mma16816(acc0[2*ng],   ah0, bh[ng][0], bh[ng][1]);
                mma16816(acc1[2*ng],   ah1, bh[ng][0], bh[ng][1]);
                mma16816(acc0[2*ng+1], ah0, bh[ng][2], bh[ng][3]);
                mma16816(acc1[2*ng+1], ah1, bh[ng][2], bh[ng][3]);
            }
            // pass 2: lo*hi — dependent on pass 1, distance 16 issues
#pragma unroll
            for (int ng = 0; ng < 4; ng++) {
                mma16816(acc0[2*ng],   al0, bh[ng][0], bh[ng][1]);
                mma16816(acc1[2*ng],   al1, bh[ng][0], bh[ng][1]);
                mma16816(acc0[2*ng+1], al0, bh[ng][2], bh[ng][3]);
                mma16816(acc1[2*ng+1], al1, bh[ng][2], bh[ng][3]);
            }
            // pass 3: hi*lo — dependent on pass 2, distance 16 issues
#pragma unroll
            for (int ng = 0; ng < 4; ng++) {
                mma16816(acc0[2*ng],   ah0, bl[ng][0], bl[ng][1]);
                mma16816(acc1[2*ng],   ah1, bl[ng][0], bl[ng][1]);
                mma16816(acc0[2*ng+1], ah0, bl[ng][2], bl[ng][3]);
                mma16816(acc1[2*ng+1], ah1, bl[ng][2], bl[ng][3]);
            }
        }

        if (c < NCHUNK - 1) {
            stsA((c + 1) & 1);
            asm volatile("cp.async.wait_group 0;" ::: "memory");
        }
        __syncthreads();
    }

    // ---------------- epilogue: per-warp relu-dot over its 64 cols --------
    float b2v = b2[0];
    uint32_t ub0 = sb + SM_UP + (uint32_t)((nwarp * 64 + (lane & 3) * 2) * 4);
    uint32_t wb0 = sb + SM_W2 + (uint32_t)((nwarp * 64 + (lane & 3) * 2) * 4);
    int row0 = mwarp * 32 + (lane >> 2);

#pragma unroll 1
    for (int b = 0; b < NBATCH; b++) {
        u64 s00 = 0ull, s01 = 0ull, s10 = 0ull, s11 = 0ull;
        uint32_t ub = ub0 + (uint32_t)b * 1024u;
#pragma unroll
        for (int j = 0; j < 8; j++) {
            u64 u2 = lds_b64(ub + j * 32);
            u64 w2 = lds_b64(wb0 + j * 32);
            ffma2(s00, relu2(add2(pack2f(acc0[j][0], acc0[j][1]), u2)), w2);
            ffma2(s01, relu2(add2(pack2f(acc0[j][2], acc0[j][3]), u2)), w2);
            ffma2(s10, relu2(add2(pack2f(acc1[j][0], acc1[j][1]), u2)), w2);
            ffma2(s11, relu2(add2(pack2f(acc1[j][2], acc1[j][3]), u2)), w2);
        }
        float lo, hi, r00, r01, r10, r11;
        unpack2(s00, lo, hi); r00 = lo + hi;
        unpack2(s01, lo, hi); r01 = lo + hi;
        unpack2(s10, lo, hi); r10 = lo + hi;
        unpack2(s11, lo, hi); r11 = lo + hi;
        r00 += __shfl_xor_sync(0xffffffffu, r00, 1);
        r00 += __shfl_xor_sync(0xffffffffu, r00, 2);
        r01 += __shfl_xor_sync(0xffffffffu, r01, 1);
        r01 += __shfl_xor_sync(0xffffffffu, r01, 2);
        r10 += __shfl_xor_sync(0xffffffffu, r10, 1);
        r10 += __shfl_xor_sync(0xffffffffu, r10, 2);
        r11 += __shfl_xor_sync(0xffffffffu, r11, 1);
        r11 += __shfl_xor_sync(0xffffffffu, r11, 2);
        if ((lane & 3) == 0) {
            float* pb = (float*)(smem + SM_PART) + (nwarp * 16 + b) * 64;
            pb[row0]      = r00;
            pb[row0 + 8]  = r01;
            pb[row0 + 16] = r10;
            pb[row0 + 24] = r11;
        }
    }
    __syncthreads();

    // combine the 4 n-slices: 1024 outputs = 16 b x 64 rows
#pragma unroll
    for (int i = 0; i < 4; i++) {
        int idx = tid + i * NTHREADS;       // 0..1023
        int row = idx & 63, b = idx >> 6;
        float v = b2v;
#pragma unroll
        for (int nw = 0; nw < 4; nw++)
            v += ((const float*)(smem + SM_PART))[(nw * 16 + b) * 64 + row];
        int m = m0 + row;
        if (m < M) out[(size_t)b * M + m] = v;
    }
}

extern "C" void kernel_launch(void* const* d_in, const int* in_sizes, int n_in,
                              void* d_out, int out_size) {
    const int*   inst       = (const int*)d_in[0];
    const float* user_table = (const float*)d_in[1];
    const float* item       = (const float*)d_in[2];
    const float* W1         = (const float*)d_in[3];
    const float* b1         = (const float*)d_in[4];
    const float* W2v        = (const float*)d_in[5];
    const float* b2         = (const float*)d_in[6];
    float* out = (float*)d_out;
    int M = in_sizes[2] / DIMK;
    int ntiles = (M + TILE_M - 1) / TILE_M;

    cudaFuncSetAttribute(main_kernel,
                         cudaFuncAttributeMaxDynamicSharedMemorySize, SMEM_TOTAL);

    pre_kernel<<<24, 256>>>(inst, user_table, W1, b1);
    main_kernel<<<ntiles, NTHREADS, SMEM_TOTAL>>>(item, W2v, b2, out, M);
}

// round 11
// speedup vs baseline: 1.2409x; 1.2409x over previous
#include <cuda_runtime.h>
#include <cuda_fp16.h>
#include <cstdint>
#include <cstddef>

#define DIMK     256
#define NBATCH   16
#define TILE_M   64
#define NTHREADS 256
#define NCHUNK   8

typedef unsigned long long u64;

// ---------------- device globals ----------------
__device__ float g_up[NBATCH * DIMK];        // u@Wu + b1
__device__ __half g_Bh[DIMK * DIMK];         // B[n][k] = Wi[k][n], fp16

// ---------------- smem layout (main): 65KB, 2 CTAs/SM ----------------
#define SM_B    0                    // 2 bufs x 16KB = 32KB (fp16 hi only)
#define SM_PART 0                    // epilogue partials (16KB), reuses B
#define SM_A    32768                // 2 bufs x (4KB hi + 4KB lo) = 16KB
#define SM_UP   49152                // 16 x 256 fp32 = 16KB
#define SM_W2   65536                // 256 fp32 = 1KB
#define SMEM_TOTAL 66560

// ---------------- helpers ----------------
__device__ __forceinline__ u64 pack2f(float lo, float hi) {
    u64 r; asm("mov.b64 %0, {%1, %2};" : "=l"(r) : "f"(lo), "f"(hi)); return r;
}
__device__ __forceinline__ void unpack2(u64 v, float& lo, float& hi) {
    asm("mov.b64 {%0, %1}, %2;" : "=f"(lo), "=f"(hi) : "l"(v));
}
__device__ __forceinline__ u64 add2(u64 a, u64 b) {
    u64 r; asm("add.rn.f32x2 %0, %1, %2;" : "=l"(r) : "l"(a), "l"(b)); return r;
}
__device__ __forceinline__ void ffma2(u64& d, u64 a, u64 b) {
    asm("fma.rn.f32x2 %0, %1, %2, %0;" : "+l"(d) : "l"(a), "l"(b));
}
__device__ __forceinline__ u64 relu2(u64 x) {
    u64 r;
    asm("{\n\t.reg .f32 lo, hi;\n\t"
        "mov.b64 {lo, hi}, %1;\n\t"
        "max.f32 lo, lo, 0f00000000;\n\t"
        "max.f32 hi, hi, 0f00000000;\n\t"
        "mov.b64 %0, {lo, hi};\n\t}" : "=l"(r) : "l"(x));
    return r;
}
__device__ __forceinline__ u64 lds_b64(uint32_t addr) {
    u64 r; asm volatile("ld.shared.b64 %0, [%1];" : "=l"(r) : "r"(addr)); return r;
}
__device__ __forceinline__ void cp_async16(uint32_t dst, const void* src) {
    asm volatile("cp.async.cg.shared.global [%0], [%1], 16;" :: "r"(dst), "l"(src));
}
__device__ __forceinline__ void ldsm4(uint32_t* r, uint32_t addr) {
    asm volatile("ldmatrix.sync.aligned.m8n8.x4.shared.b16 {%0,%1,%2,%3}, [%4];"
        : "=r"(r[0]), "=r"(r[1]), "=r"(r[2]), "=r"(r[3]) : "r"(addr));
}
__device__ __forceinline__ void mma16816(float* c, const uint32_t* a,
                                         uint32_t b0, uint32_t b1) {
    asm volatile("mma.sync.aligned.m16n8k16.row.col.f32.f16.f16.f32 "
        "{%0,%1,%2,%3}, {%4,%5,%6,%7}, {%8,%9}, {%0,%1,%2,%3};"
        : "+f"(c[0]), "+f"(c[1]), "+f"(c[2]), "+f"(c[3])
        : "r"(a[0]), "r"(a[1]), "r"(a[2]), "r"(a[3]), "r"(b0), "r"(b1));
}
// split two fp32 into packed fp16 hi and lo words
__device__ __forceinline__ uint32_t split2h(float x, float y, uint32_t& lp) {
    __half h0 = __float2half_rn(x);
    __half h1 = __float2half_rn(y);
    __half l0 = __float2half_rn(x - __half2float(h0));
    __half l1 = __float2half_rn(y - __half2float(h1));
    __half2 hh; hh.x = h0; hh.y = h1;
    __half2 ll; ll.x = l0; ll.y = l1;
    lp = *reinterpret_cast<uint32_t*>(&ll);
    return *reinterpret_cast<uint32_t*>(&hh);
}
// row-pair layout: 64B logical rows packed into 128B smem rows, XOR-swizzled
__device__ __forceinline__ uint32_t swoff(int row, int kc) {
    uint32_t rp = (uint32_t)row >> 1;
    uint32_t c8 = (uint32_t)((row & 1) << 2) | (uint32_t)kc;
    return rp * 128u + ((c8 ^ (rp & 7u)) << 4);
}

// ---------------- fused pre: convB (blocks 0-7) + prep (blocks 8-23) ------
__global__ void pre_kernel(const int* __restrict__ inst,
                           const float* __restrict__ user_table,
                           const float* __restrict__ W1,
                           const float* __restrict__ b1) {
    __shared__ float sbuf[32 * 33];
    int tid = threadIdx.x;

    if (blockIdx.x < 8) {
        float (*tile)[33] = (float(*)[33])sbuf;
        const float* Wi = W1 + DIMK * DIMK;
        int n0 = blockIdx.x * 32;
        int tr = tid >> 5, tc = tid & 31;
        for (int kb = 0; kb < 8; kb++) {
#pragma unroll
            for (int p = 0; p < 4; p++) {
                int k = kb * 32 + p * 8 + tr;
                tile[p * 8 + tr][tc] = Wi[(size_t)k * DIMK + n0 + tc];
            }
            __syncthreads();
#pragma unroll
            for (int p = 0; p < 4; p++) {
                int nl = p * 8 + tr;
                float x = tile[tc][nl];
                g_Bh[(size_t)(n0 + nl) * DIMK + kb * 32 + tc] = __float2half_rn(x);
            }
            __syncthreads();
        }
    } else {
        float* u = sbuf;
        int b = blockIdx.x - 8;
        bool w64 = true;
#pragma unroll
        for (int i = 1; i < 16; i += 2) w64 = w64 && (inst[i] == 0);
        int row = w64 ? inst[2 * b] : inst[b];
        if (tid < 64)
            ((float4*)u)[tid] = ((const float4*)(user_table + (size_t)row * DIMK))[tid];
        __syncthreads();
        int d = tid;
        float acc = 0.f;
#pragma unroll 8
        for (int k = 0; k < DIMK; k++)
            acc = fmaf(u[k], W1[(size_t)k * DIMK + d], acc);
        g_up[b * DIMK + d] = acc + b1[d];
    }
}

// ---------------- main: fp16 2-product split, 2 CTA/SM ---------------------
__global__ void __launch_bounds__(NTHREADS, 2)
main_kernel(const float* __restrict__ item,
            const float* __restrict__ W2v, const float* __restrict__ b2,
            float* __restrict__ out, int M) {
    extern __shared__ __align__(1024) char smem[];
    uint32_t sb = (uint32_t)__cvta_generic_to_shared(smem);
    int tid = threadIdx.x, wid = tid >> 5, lane = tid & 31;
    int mwarp = wid >> 2, nwarp = wid & 3;      // 2 x 4 warp grid
    int m0 = blockIdx.x * TILE_M;

    // stage up / w2
    for (int i = tid; i < NBATCH * DIMK; i += NTHREADS)
        ((float*)(smem + SM_UP))[i] = g_up[i];
    if (tid < 64)
        ((float4*)(smem + SM_W2))[tid] = ((const float4*)W2v)[tid];

    // B chunk c (32 k, fp16 hi only) -> 16KB buf
    auto loadB = [&](int c, int buf) {
        uint32_t base = sb + SM_B + (uint32_t)buf * 16384u;
#pragma unroll
        for (int i = 0; i < 4; i++) {
            int id = tid + i * NTHREADS;       // 0..1023
            int n = id >> 2, kc = id & 3;
            cp_async16(base + swoff(n, kc),
                       (const char*)g_Bh + (size_t)n * 512 + (size_t)c * 64
                                         + (size_t)kc * 16);
        }
        asm volatile("cp.async.commit_group;" ::: "memory");
    };

    // A: thread owns (row tid>>2, 8-k group kq=tid&3)
    float4 pre[2];
    auto loadA = [&](int c) {
        int r = tid >> 2, kq = tid & 3;
        int m = m0 + r;
        pre[0] = make_float4(0.f, 0.f, 0.f, 0.f);
        pre[1] = pre[0];
        if (m < M) {
            const float4* p = (const float4*)(item + (size_t)m * DIMK + c * 32 + kq * 8);
            pre[0] = p[0]; pre[1] = p[1];
        }
    };
    auto stsA = [&](int buf) {
        int r = tid >> 2, kq = tid & 3;
        uint32_t h[4], l[4];
        h[0] = split2h(pre[0].x, pre[0].y, l[0]);
        h[1] = split2h(pre[0].z, pre[0].w, l[1]);
        h[2] = split2h(pre[1].x, pre[1].y, l[2]);
        h[3] = split2h(pre[1].z, pre[1].w, l[3]);
        uint32_t off = SM_A + (uint32_t)buf * 8192u + swoff(r, kq);
        *(uint4*)(smem + off)        = make_uint4(h[0], h[1], h[2], h[3]);
        *(uint4*)(smem + off + 4096) = make_uint4(l[0], l[1], l[2], l[3]);
    };

    float acc0[8][4], acc1[8][4];
#pragma unroll
    for (int j = 0; j < 8; j++)
#pragma unroll
        for (int q = 0; q < 4; q++) { acc0[j][q] = 0.f; acc1[j][q] = 0.f; }

    loadB(0, 0);
    loadA(0);
    stsA(0);
    asm volatile("cp.async.wait_group 0;" ::: "memory");
    __syncthreads();

#pragma unroll 1
    for (int c = 0; c < NCHUNK; c++) {
        if (c < NCHUNK - 1) {
            loadB(c + 1, (c + 1) & 1);
            loadA(c + 1);
        }

        uint32_t ab = sb + SM_A + (uint32_t)(c & 1) * 8192u;
        uint32_t bb = sb + SM_B + (uint32_t)(c & 1) * 16384u;
#pragma unroll
        for (int ks = 0; ks < 2; ks++) {
            int akc = 2 * ks + (lane >> 4);
            uint32_t a0 = ab + swoff(mwarp * 32 + (lane & 15), akc);
            uint32_t a1 = ab + swoff(mwarp * 32 + 16 + (lane & 15), akc);
            uint32_t ah0[4], ah1[4], al0[4], al1[4];
            ldsm4(ah0, a0); ldsm4(ah1, a1);
            ldsm4(al0, a0 + 4096); ldsm4(al1, a1 + 4096);

            int brow7 = (lane & 7) + ((lane >> 4) & 1) * 8;
            int bkc = 2 * ks + ((lane >> 3) & 1);

            uint32_t bh[4][4];
#pragma unroll
            for (int ng = 0; ng < 4; ng++)
                ldsm4(bh[ng], bb + swoff(nwarp * 64 + ng * 16 + brow7, bkc));

            // pass 1: hi*hi — 16 independent MMAs
#pragma unroll
            for (int ng = 0; ng < 4; ng++) {
                mma16816(acc0[2*ng],   ah0, bh[ng][0], bh[ng][1]);
                mma16816(acc1[2*ng],   ah1, bh[ng][0], bh[ng][1]);
                mma16816(acc0[2*ng+1], ah0, bh[ng][2], bh[ng][3]);
                mma16816(acc1[2*ng+1], ah1, bh[ng][2], bh[ng][3]);
            }
            // pass 2: lo*hi — distance 16 from pass 1
#pragma unroll
            for (int ng = 0; ng < 4; ng++) {
                mma16816(acc0[2*ng],   al0, bh[ng][0], bh[ng][1]);
                mma16816(acc1[2*ng],   al1, bh[ng][0], bh[ng][1]);
                mma16816(acc0[2*ng+1], al0, bh[ng][2], bh[ng][3]);
                mma16816(acc1[2*ng+1], al1, bh[ng][2], bh[ng][3]);
            }
        }

        if (c < NCHUNK - 1) {
            stsA((c + 1) & 1);
            asm volatile("cp.async.wait_group 0;" ::: "memory");
        }
        __syncthreads();
    }

    // ---------------- epilogue: per-warp relu-dot over its 64 cols --------
    float b2v = b2[0];
    uint32_t ub0 = sb + SM_UP + (uint32_t)((nwarp * 64 + (lane & 3) * 2) * 4);
    uint32_t wb0 = sb + SM_W2 + (uint32_t)((nwarp * 64 + (lane & 3) * 2) * 4);
    int row0 = mwarp * 32 + (lane >> 2);

#pragma unroll 1
    for (int b = 0; b < NBATCH; b++) {
        u64 s00 = 0ull, s01 = 0ull, s10 = 0ull, s11 = 0ull;
        uint32_t ub = ub0 + (uint32_t)b * 1024u;
#pragma unroll
        for (int j = 0; j < 8; j++) {
            u64 u2 = lds_b64(ub + j * 32);
            u64 w2 = lds_b64(wb0 + j * 32);
            ffma2(s00, relu2(add2(pack2f(acc0[j][0], acc0[j][1]), u2)), w2);
            ffma2(s01, relu2(add2(pack2f(acc0[j][2], acc0[j][3]), u2)), w2);
            ffma2(s10, relu2(add2(pack2f(acc1[j][0], acc1[j][1]), u2)), w2);
            ffma2(s11, relu2(add2(pack2f(acc1[j][2], acc1[j][3]), u2)), w2);
        }
        float lo, hi, r00, r01, r10, r11;
        unpack2(s00, lo, hi); r00 = lo + hi;
        unpack2(s01, lo, hi); r01 = lo + hi;
        unpack2(s10, lo, hi); r10 = lo + hi;
        unpack2(s11, lo, hi); r11 = lo + hi;
        r00 += __shfl_xor_sync(0xffffffffu, r00, 1);
        r00 += __shfl_xor_sync(0xffffffffu, r00, 2);
        r01 += __shfl_xor_sync(0xffffffffu, r01, 1);
        r01 += __shfl_xor_sync(0xffffffffu, r01, 2);
        r10 += __shfl_xor_sync(0xffffffffu, r10, 1);
        r10 += __shfl_xor_sync(0xffffffffu, r10, 2);
        r11 += __shfl_xor_sync(0xffffffffu, r11, 1);
        r11 += __shfl_xor_sync(0xffffffffu, r11, 2);
        if ((lane & 3) == 0) {
            float* pb = (float*)(smem + SM_PART) + (nwarp * 16 + b) * 64;
            pb[row0]      = r00;
            pb[row0 + 8]  = r01;
            pb[row0 + 16] = r10;
            pb[row0 + 24] = r11;
        }
    }
    __syncthreads();

    // combine the 4 n-slices: 1024 outputs = 16 b x 64 rows
#pragma unroll
    for (int i = 0; i < 4; i++) {
        int idx = tid + i * NTHREADS;       // 0..1023
        int row = idx & 63, b = idx >> 6;
        float v = b2v;
#pragma unroll
        for (int nw = 0; nw < 4; nw++)
            v += ((const float*)(smem + SM_PART))[(nw * 16 + b) * 64 + row];
        int m = m0 + row;
        if (m < M) out[(size_t)b * M + m] = v;
    }
}

extern "C" void kernel_launch(void* const* d_in, const int* in_sizes, int n_in,
                              void* d_out, int out_size) {
    const int*   inst       = (const int*)d_in[0];
    const float* user_table = (const float*)d_in[1];
    const float* item       = (const float*)d_in[2];
    const float* W1         = (const float*)d_in[3];
    const float* b1         = (const float*)d_in[4];
    const float* W2v        = (const float*)d_in[5];
    const float* b2         = (const float*)d_in[6];
    float* out = (float*)d_out;
    int M = in_sizes[2] / DIMK;
    int ntiles = (M + TILE_M - 1) / TILE_M;

    cudaFuncSetAttribute(main_kernel,
                         cudaFuncAttributeMaxDynamicSharedMemorySize, SMEM_TOTAL);

    pre_kernel<<<24, 256>>>(inst, user_table, W1, b1);
    main_kernel<<<ntiles, NTHREADS, SMEM_TOTAL>>>(item, W2v, b2, out, M);
}

// round 12
// speedup vs baseline: 1.4917x; 1.2021x over previous
#include <cuda_runtime.h>
#include <cuda_fp16.h>
#include <cstdint>
#include <cstddef>

#define DIMK     256
#define NBATCH   16
#define TILE_M   64
#define NTHREADS 256
#define NCHUNK   8

typedef unsigned long long u64;

// ---------------- device globals ----------------
__device__ float g_up[NBATCH * DIMK];        // u@Wu + b1
__device__ __half g_Bh[DIMK * DIMK];         // B[n][k] = Wi[k][n], fp16

// ---------------- smem layout (main): 57KB, 2 CTAs/SM ----------------
#define SM_B    0                    // 2 bufs x 16KB = 32KB
#define SM_PART 0                    // epilogue partials (16KB), reuses B
#define SM_A    32768                // 2 bufs x 4KB = 8KB (fp16 hi only)
#define SM_UP   40960                // 16 x 256 fp32 = 16KB
#define SM_W2   57344                // 256 fp32 = 1KB
#define SMEM_TOTAL 58368

// ---------------- helpers ----------------
__device__ __forceinline__ u64 pack2f(float lo, float hi) {
    u64 r; asm("mov.b64 %0, {%1, %2};" : "=l"(r) : "f"(lo), "f"(hi)); return r;
}
__device__ __forceinline__ void unpack2(u64 v, float& lo, float& hi) {
    asm("mov.b64 {%0, %1}, %2;" : "=f"(lo), "=f"(hi) : "l"(v));
}
__device__ __forceinline__ u64 add2(u64 a, u64 b) {
    u64 r; asm("add.rn.f32x2 %0, %1, %2;" : "=l"(r) : "l"(a), "l"(b)); return r;
}
__device__ __forceinline__ void ffma2(u64& d, u64 a, u64 b) {
    asm("fma.rn.f32x2 %0, %1, %2, %0;" : "+l"(d) : "l"(a), "l"(b));
}
__device__ __forceinline__ u64 relu2(u64 x) {
    u64 r;
    asm("{\n\t.reg .f32 lo, hi;\n\t"
        "mov.b64 {lo, hi}, %1;\n\t"
        "max.f32 lo, lo, 0f00000000;\n\t"
        "max.f32 hi, hi, 0f00000000;\n\t"
        "mov.b64 %0, {lo, hi};\n\t}" : "=l"(r) : "l"(x));
    return r;
}
__device__ __forceinline__ u64 lds_b64(uint32_t addr) {
    u64 r; asm volatile("ld.shared.b64 %0, [%1];" : "=l"(r) : "r"(addr)); return r;
}
__device__ __forceinline__ void cp_async16(uint32_t dst, const void* src) {
    asm volatile("cp.async.cg.shared.global [%0], [%1], 16;" :: "r"(dst), "l"(src));
}
__device__ __forceinline__ void ldsm4(uint32_t* r, uint32_t addr) {
    asm volatile("ldmatrix.sync.aligned.m8n8.x4.shared.b16 {%0,%1,%2,%3}, [%4];"
        : "=r"(r[0]), "=r"(r[1]), "=r"(r[2]), "=r"(r[3]) : "r"(addr));
}
__device__ __forceinline__ void mma16816(float* c, const uint32_t* a,
                                         uint32_t b0, uint32_t b1) {
    asm volatile("mma.sync.aligned.m16n8k16.row.col.f32.f16.f16.f32 "
        "{%0,%1,%2,%3}, {%4,%5,%6,%7}, {%8,%9}, {%0,%1,%2,%3};"
        : "+f"(c[0]), "+f"(c[1]), "+f"(c[2]), "+f"(c[3])
        : "r"(a[0]), "r"(a[1]), "r"(a[2]), "r"(a[3]), "r"(b0), "r"(b1));
}
__device__ __forceinline__ uint32_t cvt2h(float x, float y) {
    __half2 h = __floats2half2_rn(x, y);
    return *reinterpret_cast<uint32_t*>(&h);
}
// row-pair layout: 64B logical rows packed into 128B smem rows, XOR-swizzled
__device__ __forceinline__ uint32_t swoff(int row, int kc) {
    uint32_t rp = (uint32_t)row >> 1;
    uint32_t c8 = (uint32_t)((row & 1) << 2) | (uint32_t)kc;
    return rp * 128u + ((c8 ^ (rp & 7u)) << 4);
}

// ---------------- fused pre: convB (blocks 0-7) + prep (blocks 8-23) ------
__global__ void pre_kernel(const int* __restrict__ inst,
                           const float* __restrict__ user_table,
                           const float* __restrict__ W1,
                           const float* __restrict__ b1) {
    __shared__ float sbuf[32 * 33];
    int tid = threadIdx.x;

    if (blockIdx.x < 8) {
        float (*tile)[33] = (float(*)[33])sbuf;
        const float* Wi = W1 + DIMK * DIMK;
        int n0 = blockIdx.x * 32;
        int tr = tid >> 5, tc = tid & 31;
        for (int kb = 0; kb < 8; kb++) {
#pragma unroll
            for (int p = 0; p < 4; p++) {
                int k = kb * 32 + p * 8 + tr;
                tile[p * 8 + tr][tc] = Wi[(size_t)k * DIMK + n0 + tc];
            }
            __syncthreads();
#pragma unroll
            for (int p = 0; p < 4; p++) {
                int nl = p * 8 + tr;
                float x = tile[tc][nl];
                g_Bh[(size_t)(n0 + nl) * DIMK + kb * 32 + tc] = __float2half_rn(x);
            }
            __syncthreads();
        }
    } else {
        float* u = sbuf;
        int b = blockIdx.x - 8;
        bool w64 = true;
#pragma unroll
        for (int i = 1; i < 16; i += 2) w64 = w64 && (inst[i] == 0);
        int row = w64 ? inst[2 * b] : inst[b];
        if (tid < 64)
            ((float4*)u)[tid] = ((const float4*)(user_table + (size_t)row * DIMK))[tid];
        __syncthreads();
        int d = tid;
        float acc = 0.f;
#pragma unroll 8
        for (int k = 0; k < DIMK; k++)
            acc = fmaf(u[k], W1[(size_t)k * DIMK + d], acc);
        g_up[b * DIMK + d] = acc + b1[d];
    }
}

// ---------------- main: single-product fp16, 2 CTA/SM ---------------------
__global__ void __launch_bounds__(NTHREADS, 2)
main_kernel(const float* __restrict__ item,
            const float* __restrict__ W2v, const float* __restrict__ b2,
            float* __restrict__ out, int M) {
    extern __shared__ __align__(1024) char smem[];
    uint32_t sb = (uint32_t)__cvta_generic_to_shared(smem);
    int tid = threadIdx.x, wid = tid >> 5, lane = tid & 31;
    int mwarp = wid >> 2, nwarp = wid & 3;      // 2 x 4 warp grid
    int m0 = blockIdx.x * TILE_M;

    // stage up / w2
    for (int i = tid; i < NBATCH * DIMK; i += NTHREADS)
        ((float*)(smem + SM_UP))[i] = g_up[i];
    if (tid < 64)
        ((float4*)(smem + SM_W2))[tid] = ((const float4*)W2v)[tid];

    // B chunk c (32 k) -> 16KB buf
    auto loadB = [&](int c, int buf) {
        uint32_t base = sb + SM_B + (uint32_t)buf * 16384u;
#pragma unroll
        for (int i = 0; i < 4; i++) {
            int id = tid + i * NTHREADS;       // 0..1023
            int n = id >> 2, kc = id & 3;
            cp_async16(base + swoff(n, kc),
                       (const char*)g_Bh + (size_t)n * 512 + (size_t)c * 64
                                         + (size_t)kc * 16);
        }
        asm volatile("cp.async.commit_group;" ::: "memory");
    };

    // A: thread owns (row tid>>2, 8-k group kq=tid&3)
    float4 pre[2];
    auto loadA = [&](int c) {
        int r = tid >> 2, kq = tid & 3;
        int m = m0 + r;
        pre[0] = make_float4(0.f, 0.f, 0.f, 0.f);
        pre[1] = pre[0];
        if (m < M) {
            const float4* p = (const float4*)(item + (size_t)m * DIMK + c * 32 + kq * 8);
            pre[0] = p[0]; pre[1] = p[1];
        }
    };
    auto stsA = [&](int buf) {
        int r = tid >> 2, kq = tid & 3;
        uint32_t h[4];
        h[0] = cvt2h(pre[0].x, pre[0].y);
        h[1] = cvt2h(pre[0].z, pre[0].w);
        h[2] = cvt2h(pre[1].x, pre[1].y);
        h[3] = cvt2h(pre[1].z, pre[1].w);
        uint32_t off = SM_A + (uint32_t)buf * 4096u + swoff(r, kq);
        *(uint4*)(smem + off) = make_uint4(h[0], h[1], h[2], h[3]);
    };

    float acc0[8][4], acc1[8][4];
#pragma unroll
    for (int j = 0; j < 8; j++)
#pragma unroll
        for (int q = 0; q < 4; q++) { acc0[j][q] = 0.f; acc1[j][q] = 0.f; }

    loadB(0, 0);
    loadA(0);
    stsA(0);
    asm volatile("cp.async.wait_group 0;" ::: "memory");
    __syncthreads();

#pragma unroll 1
    for (int c = 0; c < NCHUNK; c++) {
        if (c < NCHUNK - 1) {
            loadB(c + 1, (c + 1) & 1);
            loadA(c + 1);
        }

        uint32_t ab = sb + SM_A + (uint32_t)(c & 1) * 4096u;
        uint32_t bb = sb + SM_B + (uint32_t)(c & 1) * 16384u;
#pragma unroll
        for (int ks = 0; ks < 2; ks++) {
            int akc = 2 * ks + (lane >> 4);
            uint32_t ah0[4], ah1[4];
            ldsm4(ah0, ab + swoff(mwarp * 32 + (lane & 15), akc));
            ldsm4(ah1, ab + swoff(mwarp * 32 + 16 + (lane & 15), akc));

            int brow7 = (lane & 7) + ((lane >> 4) & 1) * 8;
            int bkc = 2 * ks + ((lane >> 3) & 1);

            uint32_t bh[4][4];
#pragma unroll
            for (int ng = 0; ng < 4; ng++)
                ldsm4(bh[ng], bb + swoff(nwarp * 64 + ng * 16 + brow7, bkc));

            // 16 independent MMAs (one per accumulator)
#pragma unroll
            for (int ng = 0; ng < 4; ng++) {
                mma16816(acc0[2*ng],   ah0, bh[ng][0], bh[ng][1]);
                mma16816(acc1[2*ng],   ah1, bh[ng][0], bh[ng][1]);
                mma16816(acc0[2*ng+1], ah0, bh[ng][2], bh[ng][3]);
                mma16816(acc1[2*ng+1], ah1, bh[ng][2], bh[ng][3]);
            }
        }

        if (c < NCHUNK - 1) {
            stsA((c + 1) & 1);
            asm volatile("cp.async.wait_group 0;" ::: "memory");
        }
        __syncthreads();
    }

    // ---------------- epilogue: per-warp relu-dot over its 64 cols --------
    float b2v = b2[0];
    uint32_t ub0 = sb + SM_UP + (uint32_t)((nwarp * 64 + (lane & 3) * 2) * 4);
    uint32_t wb0 = sb + SM_W2 + (uint32_t)((nwarp * 64 + (lane & 3) * 2) * 4);
    int row0 = mwarp * 32 + (lane >> 2);

    // hoist w2 (b-invariant)
    u64 w2r[8];
#pragma unroll
    for (int j = 0; j < 8; j++) w2r[j] = lds_b64(wb0 + j * 32);

#pragma unroll 1
    for (int b = 0; b < NBATCH; b++) {
        u64 s00 = 0ull, s01 = 0ull, s10 = 0ull, s11 = 0ull;
        uint32_t ub = ub0 + (uint32_t)b * 1024u;
#pragma unroll
        for (int j = 0; j < 8; j++) {
            u64 u2 = lds_b64(ub + j * 32);
            ffma2(s00, relu2(add2(pack2f(acc0[j][0], acc0[j][1]), u2)), w2r[j]);
            ffma2(s01, relu2(add2(pack2f(acc0[j][2], acc0[j][3]), u2)), w2r[j]);
            ffma2(s10, relu2(add2(pack2f(acc1[j][0], acc1[j][1]), u2)), w2r[j]);
            ffma2(s11, relu2(add2(pack2f(acc1[j][2], acc1[j][3]), u2)), w2r[j]);
        }
        float lo, hi, r00, r01, r10, r11;
        unpack2(s00, lo, hi); r00 = lo + hi;
        unpack2(s01, lo, hi); r01 = lo + hi;
        unpack2(s10, lo, hi); r10 = lo + hi;
        unpack2(s11, lo, hi); r11 = lo + hi;
        r00 += __shfl_xor_sync(0xffffffffu, r00, 1);
        r00 += __shfl_xor_sync(0xffffffffu, r00, 2);
        r01 += __shfl_xor_sync(0xffffffffu, r01, 1);
        r01 += __shfl_xor_sync(0xffffffffu, r01, 2);
        r10 += __shfl_xor_sync(0xffffffffu, r10, 1);
        r10 += __shfl_xor_sync(0xffffffffu, r10, 2);
        r11 += __shfl_xor_sync(0xffffffffu, r11, 1);
        r11 += __shfl_xor_sync(0xffffffffu, r11, 2);
        if ((lane & 3) == 0) {
            float* pb = (float*)(smem + SM_PART) + (nwarp * 16 + b) * 64;
            pb[row0]      = r00;
            pb[row0 + 8]  = r01;
            pb[row0 + 16] = r10;
            pb[row0 + 24] = r11;
        }
    }
    __syncthreads();

    // combine the 4 n-slices: 1024 outputs = 16 b x 64 rows
#pragma unroll
    for (int i = 0; i < 4; i++) {
        int idx = tid + i * NTHREADS;       // 0..1023
        int row = idx & 63, b = idx >> 6;
        float v = b2v;
#pragma unroll
        for (int nw = 0; nw < 4; nw++)
            v += ((const float*)(smem + SM_PART))[(nw * 16 + b) * 64 + row];
        int m = m0 + row;
        if (m < M) out[(size_t)b * M + m] = v;
    }
}

extern "C" void kernel_launch(void* const* d_in, const int* in_sizes, int n_in,
                              void* d_out, int out_size) {
    const int*   inst       = (const int*)d_in[0];
    const float* user_table = (const float*)d_in[1];
    const float* item       = (const float*)d_in[2];
    const float* W1         = (const float*)d_in[3];
    const float* b1         = (const float*)d_in[4];
    const float* W2v        = (const float*)d_in[5];
    const float* b2         = (const float*)d_in[6];
    float* out = (float*)d_out;
    int M = in_sizes[2] / DIMK;
    int ntiles = (M + TILE_M - 1) / TILE_M;

    cudaFuncSetAttribute(main_kernel,
                         cudaFuncAttributeMaxDynamicSharedMemorySize, SMEM_TOTAL);

    pre_kernel<<<24, 256>>>(inst, user_table, W1, b1);
    main_kernel<<<ntiles, NTHREADS, SMEM_TOTAL>>>(item, W2v, b2, out, M);
}